// round 15
// baseline (speedup 1.0000x reference)
#include <cuda_runtime.h>
#include <cuda_fp16.h>
#include <cstdint>

#define BATCH 1024
#define NV 6890
#define NJ 24
#define NSHAPE 10
#define KPOSE 207
#define N3 (NV*3)          // 20670
#define KUSED 219          // 207 pf + 10 betas + 2 ones (vt_hi, vt_lo)
#define NCHUNK 14          // operand storage granularity: 14 chunks of k=16
#define CHUNK_ELEMS 2048   // 128 rows x 16 k
#define NTILES 162         // ceil(20670/128)
#define MTILES 8           // 1024/128
#define KCH 7              // gemm mainloop chunks of k=32

// merged prep partition
#define PB_BLOCKS ((KUSED*N3 + 255)/256)
#define PW_BLOCKS ((NJ*NV + 255)/256)

// LBS kernel tiling
#define LVB 128            // vertices per block
#define LBB 32             // batches per block
#define NSLICE 8           // slices of 4 batches
#define TST 64             // T row stride (floats) = 16 float4 groups, swizzled
#define SLICE_ELEMS 1536   // 48 cols x 32 k fp16

__constant__ int c_parents[NJ] = {-1,0,0,0,1,2,3,4,5,6,7,8,9,9,9,12,13,14,16,17,18,19,20,21};

// device-global scratch (zero-initialized; pads never written)
__device__ float g_JRs[NJ*3*NSHAPE];
__device__ float g_Jbase[NJ*3];
// Arel pre-swizzled fp16: one 1536-elem chunk per 4-batch slice (k>=24 stays 0)
__device__ __half g_Arelh[(BATCH/4)*SLICE_ELEMS];
__device__ __half g_Whh[NJ*NV];                  // lbs_weights^T fp16 hi
__device__ __half g_Whl[NJ*NV];                  // lbs_weights^T fp16 lo
__device__ float g_vposed[BATCH*N3];             // 84.7 MB scratch
__device__ __half g_Asw_h[MTILES*NCHUNK*CHUNK_ELEMS];
__device__ __half g_Bsw_h[NTILES*NCHUNK*CHUNK_ELEMS];

__device__ __forceinline__ uint32_t smem_u32(const void* p) {
    uint32_t a;
    asm("{ .reg .u64 t; cvta.to.shared.u64 t, %1; cvt.u32.u64 %0, t; }" : "=r"(a) : "l"(p));
    return a;
}

// tile-contiguous element index within a 128x16 chunk (2 k8-tiles per row-tile)
__device__ __forceinline__ int tile_idx(int r, int kk) {
    return ((r >> 3)*2 + (kk >> 3))*64 + (r & 7)*8 + (kk & 7);
}
// 4 k8-tiles per row-tile (32-wide k)
__device__ __forceinline__ int tile_idx4(int r, int kk) {
    return ((r >> 3)*4 + (kk >> 3))*64 + (r & 7)*8 + (kk & 7);
}

#define CP16(dst, src) \
    asm volatile("cp.async.cg.shared.global [%0], [%1], 16;" :: "r"(dst), "l"(src) : "memory")

#define LDSM4(r, addr) \
    asm volatile("ldmatrix.sync.aligned.m8n8.x4.shared.b16 {%0,%1,%2,%3}, [%4];" \
                 : "=r"((r)[0]), "=r"((r)[1]), "=r"((r)[2]), "=r"((r)[3]) : "r"(addr))

#define MMA_F16(D, A, B0, B1) \
    asm volatile("mma.sync.aligned.m16n8k16.row.col.f32.f16.f16.f32 " \
                 "{%0,%1,%2,%3},{%4,%5,%6,%7},{%8,%9},{%0,%1,%2,%3};" \
                 : "+f"(D[0]), "+f"(D[1]), "+f"(D[2]), "+f"(D[3]) \
                 : "r"((A)[0]), "r"((A)[1]), "r"((A)[2]), "r"((A)[3]), "r"(B0), "r"(B1))

// ---------------------------------------------------------------------------
// Merged prep: [0, PB)       -> B operand chunks (fp16)
//              [PB, PB+PW)   -> W^T fp16 hi/lo
//              [PB+PW, +72)  -> J_regressor folding
// ---------------------------------------------------------------------------
__global__ void k_prep(const float* __restrict__ pd,
                       const float* __restrict__ sd,
                       const float* __restrict__ vt,
                       const float* __restrict__ w,
                       const float* __restrict__ JR) {
    __shared__ float red[256][12];
    int bid = blockIdx.x;
    int tid = threadIdx.x;

    if (bid < PB_BLOCKS) {
        long i = (long)bid * 256 + tid;
        if (i >= (long)KUSED * N3) return;
        int k = (int)(i / N3);
        int n = (int)(i % N3);
        __half h;
        if (k < KPOSE) {
            h = __float2half_rn(pd[(size_t)k*N3 + n]);
        } else if (k < KPOSE + NSHAPE) {
            int l = k - KPOSE;
            int v = n / 3, c = n % 3;
            h = __float2half_rn(sd[v*30 + c*10 + l]);
        } else if (k == KPOSE + NSHAPE) {
            h = __float2half_rn(vt[n]);
        } else {
            float x = vt[n];
            __half hv = __float2half_rn(x);
            h = __float2half_rn(x - __half2float(hv));
        }
        int ntile = n >> 7, c = n & 127;
        size_t base = (size_t)(ntile*NCHUNK + (k >> 4)) * CHUNK_ELEMS + tile_idx(c, k & 15);
        g_Bsw_h[base] = h;
        return;
    }

    if (bid < PB_BLOCKS + PW_BLOCKS) {
        int i = (bid - PB_BLOCKS) * 256 + tid;
        if (i >= NJ*NV) return;
        int j = i / NV, v = i % NV;
        float x = w[v*NJ + j];
        __half hi = __float2half_rn(x);
        __half lo = __float2half_rn(x - __half2float(hi));
        g_Whh[i] = hi;
        g_Whl[i] = lo;
        return;
    }

    // jreg
    int o = bid - PB_BLOCKS - PW_BLOCKS;   // 0..71
    int j = o / 3;
    int c = o % 3;
    float acc[11];
    #pragma unroll
    for (int l = 0; l < 11; l++) acc[l] = 0.f;
    for (int v = tid; v < NV; v += 256) {
        float r = JR[j*NV + v];
        const float* s = &sd[v*30 + c*10];
        #pragma unroll
        for (int l = 0; l < 10; l++) acc[l] += r * s[l];
        acc[10] += r * vt[v*3 + c];
    }
    #pragma unroll
    for (int l = 0; l < 11; l++) red[tid][l] = acc[l];
    __syncthreads();
    for (int st = 128; st > 0; st >>= 1) {
        if (tid < st) {
            #pragma unroll
            for (int l = 0; l < 11; l++) red[tid][l] += red[tid + st][l];
        }
        __syncthreads();
    }
    if (tid < 10) g_JRs[(j*3 + c)*NSHAPE + tid] = red[0][tid];
    if (tid == 10) g_Jbase[j*3 + c] = red[0][10];
}

// ---------------------------------------------------------------------------
// 8 warps per block, warp per batch. bpose staged to smem (coalesced), chain
// split across 3 lanes, Arel emitted pre-swizzled fp16 for k_lbs.
// ---------------------------------------------------------------------------
__global__ __launch_bounds__(256)
void k_joints(const float* __restrict__ betas,
              const float* __restrict__ grot,
              const float* __restrict__ bpose,
              float* __restrict__ out_joints) {
    int warp = threadIdx.x >> 5;
    int lane = threadIdx.x & 31;
    int b = blockIdx.x * 8 + warp;
    __shared__ float sBp[8][KPOSE];
    __shared__ float sJt[8][NJ*3];
    __shared__ float sA[8][NJ*12];

    for (int idx = lane; idx < KPOSE; idx += 32)
        sBp[warp][idx] = bpose[b*KPOSE + idx];

    for (int idx = lane; idx < NJ*3; idx += 32) {
        float v = g_Jbase[idx];
        const float* jr = &g_JRs[idx*NSHAPE];
        const float* be = &betas[b*NSHAPE];
        #pragma unroll
        for (int l = 0; l < NSHAPE; l++) v += jr[l]*be[l];
        sJt[warp][idx] = v;
    }
    __syncwarp();

    // A operand row (fp16, swizzled)
    int mtile = b >> 7, rloc = b & 127;
    for (int idx = lane; idx < KUSED; idx += 32) {
        float val;
        if (idx < KPOSE) {
            int rr = (idx % 9) / 3, cc = idx % 3;
            val = sBp[warp][idx] - ((rr == cc) ? 1.f : 0.f);
        } else if (idx < KPOSE + NSHAPE) {
            val = betas[b*NSHAPE + (idx - KPOSE)];
        } else {
            val = 1.f;
        }
        size_t base = (size_t)(mtile*NCHUNK + (idx >> 4)) * CHUNK_ELEMS + tile_idx(rloc, idx & 15);
        g_Asw_h[base] = __float2half_rn(val);
    }

    // chain: lane m (m<3) owns row m of every A_j
    if (lane < 3) {
        int m = lane;
        float* A = sA[warp];
        const float* Bp = sBp[warp];
        const float* Jt = sJt[warp];
        A[m*4+0] = grot[b*9 + m*3 + 0];
        A[m*4+1] = grot[b*9 + m*3 + 1];
        A[m*4+2] = grot[b*9 + m*3 + 2];
        A[m*4+3] = Jt[m];
        for (int j = 1; j < NJ; j++) {
            int p = c_parents[j];
            const float* Rl = &Bp[(j-1)*9];
            float t0 = Jt[j*3+0] - Jt[p*3+0];
            float t1 = Jt[j*3+1] - Jt[p*3+1];
            float t2 = Jt[j*3+2] - Jt[p*3+2];
            float r0 = A[p*12 + m*4+0];
            float r1 = A[p*12 + m*4+1];
            float r2 = A[p*12 + m*4+2];
            float rt = A[p*12 + m*4+3];
            A[j*12 + m*4+0] = r0*Rl[0] + r1*Rl[3] + r2*Rl[6];
            A[j*12 + m*4+1] = r0*Rl[1] + r1*Rl[4] + r2*Rl[7];
            A[j*12 + m*4+2] = r0*Rl[2] + r1*Rl[5] + r2*Rl[8];
            A[j*12 + m*4+3] = r0*t0 + r1*t1 + r2*t2 + rt;
        }
    }
    __syncwarp();

    if (lane < NJ) {
        int j = lane;
        const float* Aj = &sA[warp][j*12];
        float jt0 = sJt[warp][j*3+0], jt1 = sJt[warp][j*3+1], jt2 = sJt[warp][j*3+2];
        // pre-swizzled fp16 Arel chunk: slice = b/4, col n = (b%4)*12 + r, k = j
        __half* dst = &g_Arelh[(size_t)(b >> 2)*SLICE_ELEMS];
        int ncol0 = (b & 3)*12;
        #pragma unroll
        for (int m = 0; m < 3; m++) {
            float r0 = Aj[m*4+0], r1 = Aj[m*4+1], r2 = Aj[m*4+2];
            float t = Aj[m*4+3];
            out_joints[(b*NJ + j)*3 + m] = t;
            float trel = t - (r0*jt0 + r1*jt1 + r2*jt2);
            dst[tile_idx4(ncol0 + m*4 + 0, j)] = __float2half_rn(r0);
            dst[tile_idx4(ncol0 + m*4 + 1, j)] = __float2half_rn(r1);
            dst[tile_idx4(ncol0 + m*4 + 2, j)] = __float2half_rn(r2);
            dst[tile_idx4(ncol0 + m*4 + 3, j)] = __float2half_rn(trel);
        }
    }
}

// ---------------------------------------------------------------------------
// GEMM: v_posed = A(1024x224) @ B(224x20670), fp16 1-pass, k=32 chunks.
// CTA 128x128, 8 warps (4m x 2n), 3-stage cp.async ring (16KB/stage).
// ---------------------------------------------------------------------------
#define STG_BYTES 16384

__global__ __launch_bounds__(256, 2)
void k_gemm() {
    __shared__ __align__(128) char sm[3][STG_BYTES];
    uint32_t sbase = smem_u32(sm);

    int tid = threadIdx.x;
    int lane = tid & 31;
    int wid = tid >> 5;
    int wm = wid & 3;
    int wn = wid >> 2;
    int g4 = lane >> 2;
    int t4 = lane & 3;
    int ntile = blockIdx.x;
    int mtile = blockIdx.y;
    int n0 = ntile * 128;
    int m0 = mtile * 128;

    const char* srcAh = (const char*)&g_Asw_h[(size_t)mtile*NCHUNK*CHUNK_ELEMS];
    const char* srcBh = (const char*)&g_Bsw_h[(size_t)ntile*NCHUNK*CHUNK_ELEMS];

    int qa = lane >> 3, ra = lane & 7;
    uint32_t offA[2], offB[4];
    #pragma unroll
    for (int mf = 0; mf < 2; mf++) {
        int tr0 = 4*wm + 2*mf;
        int t = (tr0 + (qa & 1))*2 + (qa >> 1);
        offA[mf] = t*128 + ra*16;
    }
    #pragma unroll
    for (int p = 0; p < 4; p++) {
        int gA = 8*wn + 2*p;
        int t = (gA + (qa >> 1))*2 + (qa & 1);
        offB[p] = t*128 + ra*16;
    }

    auto load_chunk = [&](int s, int ck) {
        uint32_t d = sbase + s*STG_BYTES;
        size_t co = (size_t)ck * 8192;
        CP16(d + tid*16,          srcAh + co + tid*16);
        CP16(d + 4096 + tid*16,   srcAh + co + 4096 + tid*16);
        CP16(d + 8192 + tid*16,   srcBh + co + tid*16);
        CP16(d + 12288 + tid*16,  srcBh + co + 4096 + tid*16);
        asm volatile("cp.async.commit_group;" ::: "memory");
    };

    float d[2][8][4];
    #pragma unroll
    for (int mf = 0; mf < 2; mf++)
        #pragma unroll
        for (int f = 0; f < 8; f++)
            #pragma unroll
            for (int q = 0; q < 4; q++) d[mf][f][q] = 0.f;

    load_chunk(0, 0);
    load_chunk(1, 1);

    for (int ck = 0; ck < KCH; ck++) {
        int s = ck % 3;
        if (ck < KCH-1) asm volatile("cp.async.wait_group 1;" ::: "memory");
        else            asm volatile("cp.async.wait_group 0;" ::: "memory");
        __syncthreads();
        if (ck + 2 < KCH) load_chunk((ck + 2) % 3, ck + 2);

        #pragma unroll
        for (int ks2 = 0; ks2 < 2; ks2++) {
            uint32_t sba = sbase + s*STG_BYTES + ks2*4096;
            uint32_t sbb = sbase + s*STG_BYTES + 8192 + ks2*4096;
            unsigned ah[2][4];
            #pragma unroll
            for (int mf = 0; mf < 2; mf++) LDSM4(ah[mf], sba + offA[mf]);
            #pragma unroll
            for (int p = 0; p < 4; p++) {
                unsigned bh[4];
                LDSM4(bh, sbb + offB[p]);
                #pragma unroll
                for (int mf = 0; mf < 2; mf++) {
                    MMA_F16(d[mf][2*p],   ah[mf], bh[0], bh[1]);
                    MMA_F16(d[mf][2*p+1], ah[mf], bh[2], bh[3]);
                }
            }
        }
    }

    #pragma unroll
    for (int mf = 0; mf < 2; mf++) {
        #pragma unroll
        for (int f = 0; f < 8; f++) {
            int row = m0 + 32*wm + 16*mf + g4;
            int cg = n0 + 64*wn + 8*f + 2*t4;
            if (cg < N3) {
                *(float2*)&g_vposed[(size_t)row*N3 + cg] =
                    make_float2(d[mf][f][0], d[mf][f][1]);
                *(float2*)&g_vposed[(size_t)(row+8)*N3 + cg] =
                    make_float2(d[mf][f][2], d[mf][f][3]);
            }
        }
    }
}

// ---------------------------------------------------------------------------
// LBS: block = 128 vertices x 32 batches (8 slices of 4), fp16 2-pass:
// T = (W_hi + W_lo) @ Arel_hi. Arel pre-swizzled via cp.async (race-safe).
// T tile uses 16B-granule XOR swizzle: group g of row v stored at g^(v&7)
// -> conflict-free STS.64 writes AND LDS.128 reads.
// ---------------------------------------------------------------------------
union ULbs {
    __half Wst[2][LVB*32];
    float T[LVB*TST];      // 32 KB
};

__global__ __launch_bounds__(256, 4)
void k_lbs(float* __restrict__ out_v) {
    __shared__ ULbs u;
    __shared__ __align__(128) __half sRh[2][SLICE_ELEMS];

    int tid = threadIdx.x;
    int lane = tid & 31;
    int wid = tid >> 5;
    int g4 = lane >> 2;
    int t4 = lane & 3;
    int qa = lane >> 3, ra = lane & 7;
    int v0 = blockIdx.x * LVB;
    int b0 = blockIdx.y * LBB;
    int slice0 = b0 >> 2;                 // 8 slices: slice0 .. slice0+7

    // stage W (verts x 32k)
    const __half zero = __float2half_rn(0.f);
    for (int i = tid; i < LVB*32; i += 256) {
        int v = i >> 5, k = i & 31;
        int vg = v0 + v;
        __half h = zero, l = zero;
        if (k < NJ && vg < NV) {
            h = g_Whh[k*NV + vg];
            l = g_Whl[k*NV + vg];
        }
        int ti = tile_idx4(v, k);
        u.Wst[0][ti] = h;
        u.Wst[1][ti] = l;
    }

    // prefetch Arel slices 0, 1 (3KB each; 192 threads x 16B)
    auto load_slice = [&](int buf, int s) {
        if (tid < 192)
            CP16(smem_u32(sRh[buf]) + tid*16,
                 (const char*)&g_Arelh[(size_t)(slice0 + s)*SLICE_ELEMS] + tid*16);
        asm volatile("cp.async.commit_group;" ::: "memory");
    };
    load_slice(0, 0);
    load_slice(1, 1);

    __syncthreads();   // W staged

    // extract W fragments (warp owns rows 16*wid..16*wid+15)
    uint32_t wbase = smem_u32(u.Wst[0]);
    unsigned wh[2][4], wl[2][4];
    #pragma unroll
    for (int ks = 0; ks < 2; ks++) {
        int t = (2*wid + (qa & 1))*4 + 2*ks + (qa >> 1);
        LDSM4(wh[ks], wbase + t*128 + ra*16);
        LDSM4(wl[ks], wbase + 8192 + t*128 + ra*16);
    }

    int vert = tid & 127;
    int half_ = tid >> 7;
    int vgc = v0 + vert;
    float4* T4 = (float4*)u.T;
    int vx = vert & 7;          // consumer row swizzle key

    for (int s = 0; s < NSLICE; s++) {
        if (s < NSLICE-1) asm volatile("cp.async.wait_group 1;" ::: "memory");
        else              asm volatile("cp.async.wait_group 0;" ::: "memory");
        __syncthreads();   // (A) slice s visible to all; prev T consume done

        uint32_t rb = smem_u32(sRh[s & 1]);
        float d[6][4];
        #pragma unroll
        for (int f = 0; f < 6; f++)
            #pragma unroll
            for (int q = 0; q < 4; q++) d[f][q] = 0.f;

        #pragma unroll
        for (int ks = 0; ks < 2; ks++) {
            #pragma unroll
            for (int p = 0; p < 3; p++) {
                int t = (2*p + (qa >> 1))*4 + 2*ks + (qa & 1);
                unsigned bh[4];
                LDSM4(bh, rb + t*128 + ra*16);
                MMA_F16(d[2*p],   wh[ks], bh[0], bh[1]);
                MMA_F16(d[2*p],   wl[ks], bh[0], bh[1]);
                MMA_F16(d[2*p+1], wh[ks], bh[2], bh[3]);
                MMA_F16(d[2*p+1], wl[ks], bh[2], bh[3]);
            }
        }

        // write T with XOR-swizzled 16B groups: g = col/4, phys = g ^ (row&7)
        #pragma unroll
        for (int f = 0; f < 6; f++) {
            int row = 16*wid + g4;
            int col = 8*f + 2*t4;
            int g = col >> 2;
            int off = (col & 3);
            int rx = row & 7;          // same for row and row+8
            float* p0 = &u.T[row*TST     + ((g ^ rx) << 2) + off];
            float* p1 = &u.T[(row+8)*TST + ((g ^ rx) << 2) + off];
            *(float2*)p0 = make_float2(d[f][0], d[f][1]);
            *(float2*)p1 = make_float2(d[f][2], d[f][3]);
        }
        __syncthreads();   // (B) all threads consumed sRh[s&1] and wrote T

        // safe now: nobody reads buffer s&1 anymore this slice
        if (s + 2 < NSLICE) load_slice(s & 1, s + 2);

        if (vgc < NV) {
            #pragma unroll
            for (int x = 0; x < 2; x++) {
                int bb = half_*2 + x;
                int bglob = b0 + s*4 + bb;
                int gbase = 3*bb;      // groups 3bb, 3bb+1, 3bb+2
                float4 A0 = T4[vert*16 + ((gbase    ) ^ vx)];
                float4 A1 = T4[vert*16 + ((gbase + 1) ^ vx)];
                float4 A2 = T4[vert*16 + ((gbase + 2) ^ vx)];
                size_t vp = (size_t)bglob*N3 + (size_t)vgc*3;
                float px = g_vposed[vp], py = g_vposed[vp+1], pz = g_vposed[vp+2];
                float ox = A0.x*px + A0.y*py + A0.z*pz + A0.w;
                float oy = A1.x*px + A1.y*py + A1.z*pz + A1.w;
                float oz = A2.x*px + A2.y*py + A2.z*pz + A2.w;
                size_t ob = ((size_t)bglob*NV + vgc)*3;
                out_v[ob]   = ox;
                out_v[ob+1] = oy;
                out_v[ob+2] = oz;
            }
        }
    }
}

// ---------------------------------------------------------------------------
extern "C" void kernel_launch(void* const* d_in, const int* in_sizes, int n_in,
                              void* d_out, int out_size) {
    const float* betas = (const float*)d_in[0];
    const float* grot  = (const float*)d_in[1];
    const float* bpose = (const float*)d_in[2];
    const float* vt    = (const float*)d_in[3];
    const float* sd    = (const float*)d_in[4];
    const float* pd    = (const float*)d_in[5];
    const float* JR    = (const float*)d_in[6];
    const float* w     = (const float*)d_in[7];
    float* out = (float*)d_out;
    float* out_vertices = out;
    float* out_joints = out + (size_t)BATCH*NV*3;

    k_prep<<<PB_BLOCKS + PW_BLOCKS + NJ*3, 256>>>(pd, sd, vt, w, JR);
    k_joints<<<BATCH/8, 256>>>(betas, grot, bpose, out_joints);
    k_gemm<<<dim3(NTILES, MTILES), 256>>>();
    k_lbs<<<dim3((NV + LVB - 1)/LVB, BATCH/LBB), 256>>>(out_vertices);
}

// round 16
// speedup vs baseline: 1.0655x; 1.0655x over previous
#include <cuda_runtime.h>
#include <cuda_fp16.h>
#include <cstdint>

#define BATCH 1024
#define NV 6890
#define NJ 24
#define NSHAPE 10
#define KPOSE 207
#define N3 (NV*3)          // 20670
#define KUSED 219          // 207 pf + 10 betas + 2 ones (vt_hi, vt_lo)
#define NCHUNK 14          // operand storage granularity: 14 chunks of k=16
#define CHUNK_ELEMS 2048   // 128 rows x 16 k
#define NTILES 162         // ceil(20670/128)
#define MTILES 8           // 1024/128
#define KCH 7              // gemm mainloop chunks of k=32

// merged prep partition
#define PB_BLOCKS ((KUSED*N3 + 255)/256)
#define PW_BLOCKS ((NJ*NV + 255)/256)

// LBS kernel tiling
#define LVB 128            // vertices per block
#define LBB 32             // batches per block
#define NSLICE 8           // slices of 4 batches
#define TST 64             // T row stride (floats), XOR-swizzled 16B groups
#define SLICE_ELEMS 1536   // 48 cols x 32 k fp16
#define NVT 54             // ceil(NV/128) vertex tiles
#define WT_ELEMS 4096      // W tile: 128 verts x 32 k fp16

__constant__ int c_parents[NJ] = {-1,0,0,0,1,2,3,4,5,6,7,8,9,9,9,12,13,14,16,17,18,19,20,21};

// device-global scratch (zero-initialized; pads never written)
__device__ float g_JRs[NJ*3*NSHAPE];
__device__ float g_Jbase[NJ*3];
// Arel pre-swizzled fp16: one 1536-elem chunk per 4-batch slice (k>=24 stays 0)
__device__ __half g_Arelh[(BATCH/4)*SLICE_ELEMS];
// W pre-swizzled fp16 hi/lo per vertex tile (k>=24 and verts>=NV stay 0)
__device__ __half g_Wswh[NVT*WT_ELEMS];
__device__ __half g_Wswl[NVT*WT_ELEMS];
__device__ float g_vposed[BATCH*N3];             // 84.7 MB scratch
__device__ __half g_Asw_h[MTILES*NCHUNK*CHUNK_ELEMS];
__device__ __half g_Bsw_h[NTILES*NCHUNK*CHUNK_ELEMS];

__device__ __forceinline__ uint32_t smem_u32(const void* p) {
    uint32_t a;
    asm("{ .reg .u64 t; cvta.to.shared.u64 t, %1; cvt.u32.u64 %0, t; }" : "=r"(a) : "l"(p));
    return a;
}

// tile-contiguous element index within a 128x16 chunk (2 k8-tiles per row-tile)
__device__ __forceinline__ int tile_idx(int r, int kk) {
    return ((r >> 3)*2 + (kk >> 3))*64 + (r & 7)*8 + (kk & 7);
}
// 4 k8-tiles per row-tile (32-wide k)
__device__ __forceinline__ int tile_idx4(int r, int kk) {
    return ((r >> 3)*4 + (kk >> 3))*64 + (r & 7)*8 + (kk & 7);
}

#define CP16(dst, src) \
    asm volatile("cp.async.cg.shared.global [%0], [%1], 16;" :: "r"(dst), "l"(src) : "memory")

#define LDSM4(r, addr) \
    asm volatile("ldmatrix.sync.aligned.m8n8.x4.shared.b16 {%0,%1,%2,%3}, [%4];" \
                 : "=r"((r)[0]), "=r"((r)[1]), "=r"((r)[2]), "=r"((r)[3]) : "r"(addr))

#define MMA_F16(D, A, B0, B1) \
    asm volatile("mma.sync.aligned.m16n8k16.row.col.f32.f16.f16.f32 " \
                 "{%0,%1,%2,%3},{%4,%5,%6,%7},{%8,%9},{%0,%1,%2,%3};" \
                 : "+f"(D[0]), "+f"(D[1]), "+f"(D[2]), "+f"(D[3]) \
                 : "r"((A)[0]), "r"((A)[1]), "r"((A)[2]), "r"((A)[3]), "r"(B0), "r"(B1))

// ---------------------------------------------------------------------------
// Merged prep: [0, PB)       -> B operand chunks (fp16)
//              [PB, PB+PW)   -> W^T fp16 hi/lo, pre-swizzled per vertex tile
//              [PB+PW, +72)  -> J_regressor folding
// ---------------------------------------------------------------------------
__global__ void k_prep(const float* __restrict__ pd,
                       const float* __restrict__ sd,
                       const float* __restrict__ vt,
                       const float* __restrict__ w,
                       const float* __restrict__ JR) {
    __shared__ float red[256][12];
    int bid = blockIdx.x;
    int tid = threadIdx.x;

    if (bid < PB_BLOCKS) {
        long i = (long)bid * 256 + tid;
        if (i >= (long)KUSED * N3) return;
        int k = (int)(i / N3);
        int n = (int)(i % N3);
        __half h;
        if (k < KPOSE) {
            h = __float2half_rn(pd[(size_t)k*N3 + n]);
        } else if (k < KPOSE + NSHAPE) {
            int l = k - KPOSE;
            int v = n / 3, c = n % 3;
            h = __float2half_rn(sd[v*30 + c*10 + l]);
        } else if (k == KPOSE + NSHAPE) {
            h = __float2half_rn(vt[n]);
        } else {
            float x = vt[n];
            __half hv = __float2half_rn(x);
            h = __float2half_rn(x - __half2float(hv));
        }
        int ntile = n >> 7, c = n & 127;
        size_t base = (size_t)(ntile*NCHUNK + (k >> 4)) * CHUNK_ELEMS + tile_idx(c, k & 15);
        g_Bsw_h[base] = h;
        return;
    }

    if (bid < PB_BLOCKS + PW_BLOCKS) {
        int i = (bid - PB_BLOCKS) * 256 + tid;
        if (i >= NJ*NV) return;
        int j = i / NV, v = i % NV;
        float x = w[v*NJ + j];
        __half hi = __float2half_rn(x);
        __half lo = __float2half_rn(x - __half2float(hi));
        int vtile = v >> 7, vloc = v & 127;
        size_t ti = (size_t)vtile*WT_ELEMS + tile_idx4(vloc, j);
        g_Wswh[ti] = hi;
        g_Wswl[ti] = lo;
        return;
    }

    // jreg
    int o = bid - PB_BLOCKS - PW_BLOCKS;   // 0..71
    int j = o / 3;
    int c = o % 3;
    float acc[11];
    #pragma unroll
    for (int l = 0; l < 11; l++) acc[l] = 0.f;
    for (int v = tid; v < NV; v += 256) {
        float r = JR[j*NV + v];
        const float* s = &sd[v*30 + c*10];
        #pragma unroll
        for (int l = 0; l < 10; l++) acc[l] += r * s[l];
        acc[10] += r * vt[v*3 + c];
    }
    #pragma unroll
    for (int l = 0; l < 11; l++) red[tid][l] = acc[l];
    __syncthreads();
    for (int st = 128; st > 0; st >>= 1) {
        if (tid < st) {
            #pragma unroll
            for (int l = 0; l < 11; l++) red[tid][l] += red[tid + st][l];
        }
        __syncthreads();
    }
    if (tid < 10) g_JRs[(j*3 + c)*NSHAPE + tid] = red[0][tid];
    if (tid == 10) g_Jbase[j*3 + c] = red[0][10];
}

// ---------------------------------------------------------------------------
// 8 warps per block, warp per batch. bpose staged to smem (coalesced), chain
// split across 3 lanes, Arel emitted pre-swizzled fp16 for k_lbs.
// ---------------------------------------------------------------------------
__global__ __launch_bounds__(256)
void k_joints(const float* __restrict__ betas,
              const float* __restrict__ grot,
              const float* __restrict__ bpose,
              float* __restrict__ out_joints) {
    int warp = threadIdx.x >> 5;
    int lane = threadIdx.x & 31;
    int b = blockIdx.x * 8 + warp;
    __shared__ float sBp[8][KPOSE];
    __shared__ float sJt[8][NJ*3];
    __shared__ float sA[8][NJ*12];

    for (int idx = lane; idx < KPOSE; idx += 32)
        sBp[warp][idx] = bpose[b*KPOSE + idx];

    for (int idx = lane; idx < NJ*3; idx += 32) {
        float v = g_Jbase[idx];
        const float* jr = &g_JRs[idx*NSHAPE];
        const float* be = &betas[b*NSHAPE];
        #pragma unroll
        for (int l = 0; l < NSHAPE; l++) v += jr[l]*be[l];
        sJt[warp][idx] = v;
    }
    __syncwarp();

    // A operand row (fp16, swizzled)
    int mtile = b >> 7, rloc = b & 127;
    for (int idx = lane; idx < KUSED; idx += 32) {
        float val;
        if (idx < KPOSE) {
            int rr = (idx % 9) / 3, cc = idx % 3;
            val = sBp[warp][idx] - ((rr == cc) ? 1.f : 0.f);
        } else if (idx < KPOSE + NSHAPE) {
            val = betas[b*NSHAPE + (idx - KPOSE)];
        } else {
            val = 1.f;
        }
        size_t base = (size_t)(mtile*NCHUNK + (idx >> 4)) * CHUNK_ELEMS + tile_idx(rloc, idx & 15);
        g_Asw_h[base] = __float2half_rn(val);
    }

    // chain: lane m (m<3) owns row m of every A_j
    if (lane < 3) {
        int m = lane;
        float* A = sA[warp];
        const float* Bp = sBp[warp];
        const float* Jt = sJt[warp];
        A[m*4+0] = grot[b*9 + m*3 + 0];
        A[m*4+1] = grot[b*9 + m*3 + 1];
        A[m*4+2] = grot[b*9 + m*3 + 2];
        A[m*4+3] = Jt[m];
        for (int j = 1; j < NJ; j++) {
            int p = c_parents[j];
            const float* Rl = &Bp[(j-1)*9];
            float t0 = Jt[j*3+0] - Jt[p*3+0];
            float t1 = Jt[j*3+1] - Jt[p*3+1];
            float t2 = Jt[j*3+2] - Jt[p*3+2];
            float r0 = A[p*12 + m*4+0];
            float r1 = A[p*12 + m*4+1];
            float r2 = A[p*12 + m*4+2];
            float rt = A[p*12 + m*4+3];
            A[j*12 + m*4+0] = r0*Rl[0] + r1*Rl[3] + r2*Rl[6];
            A[j*12 + m*4+1] = r0*Rl[1] + r1*Rl[4] + r2*Rl[7];
            A[j*12 + m*4+2] = r0*Rl[2] + r1*Rl[5] + r2*Rl[8];
            A[j*12 + m*4+3] = r0*t0 + r1*t1 + r2*t2 + rt;
        }
    }
    __syncwarp();

    if (lane < NJ) {
        int j = lane;
        const float* Aj = &sA[warp][j*12];
        float jt0 = sJt[warp][j*3+0], jt1 = sJt[warp][j*3+1], jt2 = sJt[warp][j*3+2];
        // pre-swizzled fp16 Arel chunk: slice = b/4, col n = (b%4)*12 + r, k = j
        __half* dst = &g_Arelh[(size_t)(b >> 2)*SLICE_ELEMS];
        int ncol0 = (b & 3)*12;
        #pragma unroll
        for (int m = 0; m < 3; m++) {
            float r0 = Aj[m*4+0], r1 = Aj[m*4+1], r2 = Aj[m*4+2];
            float t = Aj[m*4+3];
            out_joints[(b*NJ + j)*3 + m] = t;
            float trel = t - (r0*jt0 + r1*jt1 + r2*jt2);
            dst[tile_idx4(ncol0 + m*4 + 0, j)] = __float2half_rn(r0);
            dst[tile_idx4(ncol0 + m*4 + 1, j)] = __float2half_rn(r1);
            dst[tile_idx4(ncol0 + m*4 + 2, j)] = __float2half_rn(r2);
            dst[tile_idx4(ncol0 + m*4 + 3, j)] = __float2half_rn(trel);
        }
    }
}

// ---------------------------------------------------------------------------
// GEMM: v_posed = A(1024x224) @ B(224x20670), fp16 1-pass, k=32 chunks.
// CTA 128x128, 8 warps (4m x 2n), 3-stage cp.async ring (16KB/stage).
// ---------------------------------------------------------------------------
#define STG_BYTES 16384

__global__ __launch_bounds__(256, 2)
void k_gemm() {
    __shared__ __align__(128) char sm[3][STG_BYTES];
    uint32_t sbase = smem_u32(sm);

    int tid = threadIdx.x;
    int lane = tid & 31;
    int wid = tid >> 5;
    int wm = wid & 3;
    int wn = wid >> 2;
    int g4 = lane >> 2;
    int t4 = lane & 3;
    int ntile = blockIdx.x;
    int mtile = blockIdx.y;
    int n0 = ntile * 128;
    int m0 = mtile * 128;

    const char* srcAh = (const char*)&g_Asw_h[(size_t)mtile*NCHUNK*CHUNK_ELEMS];
    const char* srcBh = (const char*)&g_Bsw_h[(size_t)ntile*NCHUNK*CHUNK_ELEMS];

    int qa = lane >> 3, ra = lane & 7;
    uint32_t offA[2], offB[4];
    #pragma unroll
    for (int mf = 0; mf < 2; mf++) {
        int tr0 = 4*wm + 2*mf;
        int t = (tr0 + (qa & 1))*2 + (qa >> 1);
        offA[mf] = t*128 + ra*16;
    }
    #pragma unroll
    for (int p = 0; p < 4; p++) {
        int gA = 8*wn + 2*p;
        int t = (gA + (qa >> 1))*2 + (qa & 1);
        offB[p] = t*128 + ra*16;
    }

    auto load_chunk = [&](int s, int ck) {
        uint32_t d = sbase + s*STG_BYTES;
        size_t co = (size_t)ck * 8192;
        CP16(d + tid*16,          srcAh + co + tid*16);
        CP16(d + 4096 + tid*16,   srcAh + co + 4096 + tid*16);
        CP16(d + 8192 + tid*16,   srcBh + co + tid*16);
        CP16(d + 12288 + tid*16,  srcBh + co + 4096 + tid*16);
        asm volatile("cp.async.commit_group;" ::: "memory");
    };

    float d[2][8][4];
    #pragma unroll
    for (int mf = 0; mf < 2; mf++)
        #pragma unroll
        for (int f = 0; f < 8; f++)
            #pragma unroll
            for (int q = 0; q < 4; q++) d[mf][f][q] = 0.f;

    load_chunk(0, 0);
    load_chunk(1, 1);

    for (int ck = 0; ck < KCH; ck++) {
        int s = ck % 3;
        if (ck < KCH-1) asm volatile("cp.async.wait_group 1;" ::: "memory");
        else            asm volatile("cp.async.wait_group 0;" ::: "memory");
        __syncthreads();
        if (ck + 2 < KCH) load_chunk((ck + 2) % 3, ck + 2);

        #pragma unroll
        for (int ks2 = 0; ks2 < 2; ks2++) {
            uint32_t sba = sbase + s*STG_BYTES + ks2*4096;
            uint32_t sbb = sbase + s*STG_BYTES + 8192 + ks2*4096;
            unsigned ah[2][4];
            #pragma unroll
            for (int mf = 0; mf < 2; mf++) LDSM4(ah[mf], sba + offA[mf]);
            #pragma unroll
            for (int p = 0; p < 4; p++) {
                unsigned bh[4];
                LDSM4(bh, sbb + offB[p]);
                #pragma unroll
                for (int mf = 0; mf < 2; mf++) {
                    MMA_F16(d[mf][2*p],   ah[mf], bh[0], bh[1]);
                    MMA_F16(d[mf][2*p+1], ah[mf], bh[2], bh[3]);
                }
            }
        }
    }

    #pragma unroll
    for (int mf = 0; mf < 2; mf++) {
        #pragma unroll
        for (int f = 0; f < 8; f++) {
            int row = m0 + 32*wm + 16*mf + g4;
            int cg = n0 + 64*wn + 8*f + 2*t4;
            if (cg < N3) {
                *(float2*)&g_vposed[(size_t)row*N3 + cg] =
                    make_float2(d[mf][f][0], d[mf][f][1]);
                *(float2*)&g_vposed[(size_t)(row+8)*N3 + cg] =
                    make_float2(d[mf][f][2], d[mf][f][3]);
            }
        }
    }
}

// ---------------------------------------------------------------------------
// LBS: block = 128 vertices x 32 batches (8 slices of 4), fp16 2-pass:
// T = (W_hi + W_lo) @ Arel_hi.
// Warp tiling 4m x 2n: warp owns rows 32wm..+31, cols 24wn..+23.
// W arrives pre-swizzled via cp.async (no scalar staging); Arel per slice is
// 3 LDSM4 per warp. T tile XOR-swizzled as in R15.
// ---------------------------------------------------------------------------
union ULbs {
    __half Wst[2][WT_ELEMS];   // 16 KB (hi at 0, lo at +8192 B)
    float T[LVB*TST];          // 32 KB
};

__global__ __launch_bounds__(256, 3)
void k_lbs(float* __restrict__ out_v) {
    __shared__ ULbs u;
    __shared__ __align__(128) __half sRh[2][SLICE_ELEMS];

    int tid = threadIdx.x;
    int lane = tid & 31;
    int wid = tid >> 5;
    int wm = wid & 3;          // rows 32*wm .. +31
    int wn = wid >> 2;         // cols 24*wn .. +23
    int g4 = lane >> 2;
    int t4 = lane & 3;
    int qa = lane >> 3, ra = lane & 7;
    int v0 = blockIdx.x * LVB;
    int b0 = blockIdx.y * LBB;
    int slice0 = b0 >> 2;

    // group 0: W tiles hi+lo (16 KB) via cp.async
    {
        uint32_t wb = smem_u32(u.Wst);
        const char* srcWh = (const char*)&g_Wswh[(size_t)blockIdx.x*WT_ELEMS];
        const char* srcWl = (const char*)&g_Wswl[(size_t)blockIdx.x*WT_ELEMS];
        CP16(wb + tid*16,          srcWh + tid*16);
        CP16(wb + 4096 + tid*16,   srcWh + 4096 + tid*16);
        CP16(wb + 8192 + tid*16,   srcWl + tid*16);
        CP16(wb + 12288 + tid*16,  srcWl + 4096 + tid*16);
        asm volatile("cp.async.commit_group;" ::: "memory");
    }
    // groups 1,2: Arel slices 0,1 (3KB each; 192 threads x 16B)
    auto load_slice = [&](int buf, int s) {
        if (tid < 192)
            CP16(smem_u32(sRh[buf]) + tid*16,
                 (const char*)&g_Arelh[(size_t)(slice0 + s)*SLICE_ELEMS] + tid*16);
        asm volatile("cp.async.commit_group;" ::: "memory");
    };
    load_slice(0, 0);
    load_slice(1, 1);

    asm volatile("cp.async.wait_group 2;" ::: "memory");   // W resident
    __syncthreads();

    // extract W fragments: warp needs m16 tiles at rows 32wm+16mf
    uint32_t wbase = smem_u32(u.Wst);
    unsigned wh[2][2][4], wl[2][2][4];
    #pragma unroll
    for (int mf = 0; mf < 2; mf++) {
        #pragma unroll
        for (int ks = 0; ks < 2; ks++) {
            int t = (4*wm + 2*mf + (qa & 1))*4 + 2*ks + (qa >> 1);
            LDSM4(wh[mf][ks], wbase + t*128 + ra*16);
            LDSM4(wl[mf][ks], wbase + 8192 + t*128 + ra*16);
        }
    }

    int vert = tid & 127;
    int half_ = tid >> 7;
    int vgc = v0 + vert;
    float4* T4 = (float4*)u.T;
    int vx = vert & 7;

    for (int s = 0; s < NSLICE; s++) {
        if (s < NSLICE-1) asm volatile("cp.async.wait_group 1;" ::: "memory");
        else              asm volatile("cp.async.wait_group 0;" ::: "memory");
        __syncthreads();   // (A) slice s visible; W extraction / prev consume done

        uint32_t rb = smem_u32(sRh[s & 1]);
        // Arel B fragments: n8 tiles 3wn+p, both k16 steps in one LDSM4
        unsigned bp[3][4];
        #pragma unroll
        for (int p = 0; p < 3; p++) {
            int np = 3*wn + p;
            LDSM4(bp[p], rb + (np*4 + qa)*128 + ra*16);
        }

        float d[2][3][4];
        #pragma unroll
        for (int mf = 0; mf < 2; mf++)
            #pragma unroll
            for (int p = 0; p < 3; p++)
                #pragma unroll
                for (int q = 0; q < 4; q++) d[mf][p][q] = 0.f;

        #pragma unroll
        for (int ks = 0; ks < 2; ks++) {
            #pragma unroll
            for (int p = 0; p < 3; p++) {
                #pragma unroll
                for (int mf = 0; mf < 2; mf++) {
                    MMA_F16(d[mf][p], wh[mf][ks], bp[p][2*ks], bp[p][2*ks+1]);
                    MMA_F16(d[mf][p], wl[mf][ks], bp[p][2*ks], bp[p][2*ks+1]);
                }
            }
        }

        // write T with XOR-swizzled 16B groups: g = col/4, phys = g ^ (row&7)
        #pragma unroll
        for (int mf = 0; mf < 2; mf++) {
            #pragma unroll
            for (int p = 0; p < 3; p++) {
                int row = 32*wm + 16*mf + g4;
                int col = 24*wn + 8*p + 2*t4;
                int g = col >> 2;
                int off = col & 3;
                int rx = row & 7;
                float* p0 = &u.T[row*TST     + ((g ^ rx) << 2) + off];
                float* p1 = &u.T[(row+8)*TST + ((g ^ rx) << 2) + off];
                *(float2*)p0 = make_float2(d[mf][p][0], d[mf][p][1]);
                *(float2*)p1 = make_float2(d[mf][p][2], d[mf][p][3]);
            }
        }
        __syncthreads();   // (B) all threads consumed sRh[s&1] and wrote T

        if (s + 2 < NSLICE) load_slice(s & 1, s + 2);

        if (vgc < NV) {
            #pragma unroll
            for (int x = 0; x < 2; x++) {
                int bb = half_*2 + x;
                int bglob = b0 + s*4 + bb;
                int gbase = 3*bb;
                float4 A0 = T4[vert*16 + ((gbase    ) ^ vx)];
                float4 A1 = T4[vert*16 + ((gbase + 1) ^ vx)];
                float4 A2 = T4[vert*16 + ((gbase + 2) ^ vx)];
                size_t vp = (size_t)bglob*N3 + (size_t)vgc*3;
                float px = g_vposed[vp], py = g_vposed[vp+1], pz = g_vposed[vp+2];
                float ox = A0.x*px + A0.y*py + A0.z*pz + A0.w;
                float oy = A1.x*px + A1.y*py + A1.z*pz + A1.w;
                float oz = A2.x*px + A2.y*py + A2.z*pz + A2.w;
                size_t ob = ((size_t)bglob*NV + vgc)*3;
                out_v[ob]   = ox;
                out_v[ob+1] = oy;
                out_v[ob+2] = oz;
            }
        }
    }
}

// ---------------------------------------------------------------------------
extern "C" void kernel_launch(void* const* d_in, const int* in_sizes, int n_in,
                              void* d_out, int out_size) {
    const float* betas = (const float*)d_in[0];
    const float* grot  = (const float*)d_in[1];
    const float* bpose = (const float*)d_in[2];
    const float* vt    = (const float*)d_in[3];
    const float* sd    = (const float*)d_in[4];
    const float* pd    = (const float*)d_in[5];
    const float* JR    = (const float*)d_in[6];
    const float* w     = (const float*)d_in[7];
    float* out = (float*)d_out;
    float* out_vertices = out;
    float* out_joints = out + (size_t)BATCH*NV*3;

    k_prep<<<PB_BLOCKS + PW_BLOCKS + NJ*3, 256>>>(pd, sd, vt, w, JR);
    k_joints<<<BATCH/8, 256>>>(betas, grot, bpose, out_joints);
    k_gemm<<<dim3(NTILES, MTILES), 256>>>();
    k_lbs<<<dim3((NV + LVB - 1)/LVB, BATCH/LBB), 256>>>(out_vertices);
}

// round 17
// speedup vs baseline: 1.0666x; 1.0010x over previous
#include <cuda_runtime.h>
#include <cuda_fp16.h>
#include <cstdint>

#define BATCH 1024
#define NV 6890
#define NJ 24
#define NSHAPE 10
#define KPOSE 207
#define N3 (NV*3)          // 20670
#define KUSED 219          // 207 pf + 10 betas + 2 ones (vt_hi, vt_lo)
#define NCHUNK 14          // operand storage granularity: 14 chunks of k=16
#define CHUNK_ELEMS 2048   // 128 rows x 16 k
#define NTILES 162         // ceil(20670/128)
#define MTILES 8           // 1024/128
#define KCH 7              // gemm mainloop chunks of k=32
#define NKT 28             // 224/8 k-tiles for prep-B vectorized stores

// merged prep partition
#define PB_BLOCKS ((NKT*N3 + 255)/256)
#define PW_BLOCKS ((NJ*NV + 255)/256)

// LBS kernel tiling
#define LVB 128            // vertices per block
#define LBB 32             // batches per block
#define NSLICE 8           // slices of 4 batches
#define TST 64             // T row stride (floats), XOR-swizzled 16B groups
#define SLICE_ELEMS 1536   // 48 cols x 32 k fp16
#define NVT 54             // ceil(NV/128) vertex tiles
#define WT_ELEMS 4096      // W tile: 128 verts x 32 k fp16

__constant__ int c_parents[NJ] = {-1,0,0,0,1,2,3,4,5,6,7,8,9,9,9,12,13,14,16,17,18,19,20,21};

// device-global scratch (zero-initialized; pads never written)
__device__ float g_JRs[NJ*3*NSHAPE];
__device__ float g_Jbase[NJ*3];
__device__ __half g_Arelh[(BATCH/4)*SLICE_ELEMS];
__device__ __half g_Wswh[NVT*WT_ELEMS];
__device__ __half g_Wswl[NVT*WT_ELEMS];
__device__ float g_vposed[BATCH*N3];             // 84.7 MB scratch
__device__ __half g_Asw_h[MTILES*NCHUNK*CHUNK_ELEMS];
__device__ __half g_Bsw_h[NTILES*NCHUNK*CHUNK_ELEMS];

__device__ __forceinline__ uint32_t smem_u32(const void* p) {
    uint32_t a;
    asm("{ .reg .u64 t; cvta.to.shared.u64 t, %1; cvt.u32.u64 %0, t; }" : "=r"(a) : "l"(p));
    return a;
}

// tile-contiguous element index within a 128x16 chunk (2 k8-tiles per row-tile)
__device__ __forceinline__ int tile_idx(int r, int kk) {
    return ((r >> 3)*2 + (kk >> 3))*64 + (r & 7)*8 + (kk & 7);
}
// 4 k8-tiles per row-tile (32-wide k)
__device__ __forceinline__ int tile_idx4(int r, int kk) {
    return ((r >> 3)*4 + (kk >> 3))*64 + (r & 7)*8 + (kk & 7);
}

#define CP16(dst, src) \
    asm volatile("cp.async.cg.shared.global [%0], [%1], 16;" :: "r"(dst), "l"(src) : "memory")

#define LDSM4(r, addr) \
    asm volatile("ldmatrix.sync.aligned.m8n8.x4.shared.b16 {%0,%1,%2,%3}, [%4];" \
                 : "=r"((r)[0]), "=r"((r)[1]), "=r"((r)[2]), "=r"((r)[3]) : "r"(addr))

#define MMA_F16(D, A, B0, B1) \
    asm volatile("mma.sync.aligned.m16n8k16.row.col.f32.f16.f16.f32 " \
                 "{%0,%1,%2,%3},{%4,%5,%6,%7},{%8,%9},{%0,%1,%2,%3};" \
                 : "+f"(D[0]), "+f"(D[1]), "+f"(D[2]), "+f"(D[3]) \
                 : "r"((A)[0]), "r"((A)[1]), "r"((A)[2]), "r"((A)[3]), "r"(B0), "r"(B1))

// ---------------------------------------------------------------------------
// Merged prep: [0, PB)       -> B operand chunks (fp16), vectorized 16B stores
//              [PB, PB+PW)   -> W^T fp16 hi/lo, pre-swizzled per vertex tile
//              [PB+PW, +72)  -> J_regressor folding
// ---------------------------------------------------------------------------
__global__ void k_prep(const float* __restrict__ pd,
                       const float* __restrict__ sd,
                       const float* __restrict__ vt,
                       const float* __restrict__ w,
                       const float* __restrict__ JR) {
    __shared__ float red[256][12];
    int bid = blockIdx.x;
    int tid = threadIdx.x;

    if (bid < PB_BLOCKS) {
        long i = (long)bid * 256 + tid;
        if (i >= (long)NKT * N3) return;
        int kt = (int)(i / N3);          // 8-wide k tile
        int n = (int)(i % N3);
        __half h8[8];
        #pragma unroll
        for (int kk = 0; kk < 8; kk++) {
            int k = kt*8 + kk;
            float val = 0.f;
            if (k < KPOSE) {
                val = pd[(size_t)k*N3 + n];
            } else if (k < KPOSE + NSHAPE) {
                int l = k - KPOSE;
                int v = n / 3, c = n % 3;
                val = sd[v*30 + c*10 + l];
            } else if (k == KPOSE + NSHAPE) {
                val = vt[n];
            } else if (k == KPOSE + NSHAPE + 1) {
                float x = vt[n];
                __half hv = __float2half_rn(x);
                val = x - __half2float(hv);
            }
            h8[kk] = __float2half_rn(val);
        }
        int ntile = n >> 7, c = n & 127;
        size_t base = (size_t)(ntile*NCHUNK + (kt >> 1)) * CHUNK_ELEMS
                    + ((c >> 3)*2 + (kt & 1))*64 + (c & 7)*8;
        *(uint4*)&g_Bsw_h[base] = *(uint4*)h8;
        return;
    }

    if (bid < PB_BLOCKS + PW_BLOCKS) {
        int i = (bid - PB_BLOCKS) * 256 + tid;
        if (i >= NJ*NV) return;
        int j = i / NV, v = i % NV;
        float x = w[v*NJ + j];
        __half hi = __float2half_rn(x);
        __half lo = __float2half_rn(x - __half2float(hi));
        int vtile = v >> 7, vloc = v & 127;
        size_t ti = (size_t)vtile*WT_ELEMS + tile_idx4(vloc, j);
        g_Wswh[ti] = hi;
        g_Wswl[ti] = lo;
        return;
    }

    // jreg
    int o = bid - PB_BLOCKS - PW_BLOCKS;   // 0..71
    int j = o / 3;
    int c = o % 3;
    float acc[11];
    #pragma unroll
    for (int l = 0; l < 11; l++) acc[l] = 0.f;
    for (int v = tid; v < NV; v += 256) {
        float r = JR[j*NV + v];
        const float* s = &sd[v*30 + c*10];
        #pragma unroll
        for (int l = 0; l < 10; l++) acc[l] += r * s[l];
        acc[10] += r * vt[v*3 + c];
    }
    #pragma unroll
    for (int l = 0; l < 11; l++) red[tid][l] = acc[l];
    __syncthreads();
    for (int st = 128; st > 0; st >>= 1) {
        if (tid < st) {
            #pragma unroll
            for (int l = 0; l < 11; l++) red[tid][l] += red[tid + st][l];
        }
        __syncthreads();
    }
    if (tid < 10) g_JRs[(j*3 + c)*NSHAPE + tid] = red[0][tid];
    if (tid == 10) g_Jbase[j*3 + c] = red[0][10];
}

// ---------------------------------------------------------------------------
// 8 warps per block, warp per batch. bpose staged to smem (coalesced), chain
// split across 3 lanes, Arel emitted pre-swizzled fp16 for k_lbs.
// ---------------------------------------------------------------------------
__global__ __launch_bounds__(256)
void k_joints(const float* __restrict__ betas,
              const float* __restrict__ grot,
              const float* __restrict__ bpose,
              float* __restrict__ out_joints) {
    int warp = threadIdx.x >> 5;
    int lane = threadIdx.x & 31;
    int b = blockIdx.x * 8 + warp;
    __shared__ float sBp[8][KPOSE];
    __shared__ float sJt[8][NJ*3];
    __shared__ float sA[8][NJ*12];

    for (int idx = lane; idx < KPOSE; idx += 32)
        sBp[warp][idx] = bpose[b*KPOSE + idx];

    for (int idx = lane; idx < NJ*3; idx += 32) {
        float v = g_Jbase[idx];
        const float* jr = &g_JRs[idx*NSHAPE];
        const float* be = &betas[b*NSHAPE];
        #pragma unroll
        for (int l = 0; l < NSHAPE; l++) v += jr[l]*be[l];
        sJt[warp][idx] = v;
    }
    __syncwarp();

    // A operand row (fp16, swizzled)
    int mtile = b >> 7, rloc = b & 127;
    for (int idx = lane; idx < KUSED; idx += 32) {
        float val;
        if (idx < KPOSE) {
            int rr = (idx % 9) / 3, cc = idx % 3;
            val = sBp[warp][idx] - ((rr == cc) ? 1.f : 0.f);
        } else if (idx < KPOSE + NSHAPE) {
            val = betas[b*NSHAPE + (idx - KPOSE)];
        } else {
            val = 1.f;
        }
        size_t base = (size_t)(mtile*NCHUNK + (idx >> 4)) * CHUNK_ELEMS + tile_idx(rloc, idx & 15);
        g_Asw_h[base] = __float2half_rn(val);
    }

    // chain: lane m (m<3) owns row m of every A_j
    if (lane < 3) {
        int m = lane;
        float* A = sA[warp];
        const float* Bp = sBp[warp];
        const float* Jt = sJt[warp];
        A[m*4+0] = grot[b*9 + m*3 + 0];
        A[m*4+1] = grot[b*9 + m*3 + 1];
        A[m*4+2] = grot[b*9 + m*3 + 2];
        A[m*4+3] = Jt[m];
        for (int j = 1; j < NJ; j++) {
            int p = c_parents[j];
            const float* Rl = &Bp[(j-1)*9];
            float t0 = Jt[j*3+0] - Jt[p*3+0];
            float t1 = Jt[j*3+1] - Jt[p*3+1];
            float t2 = Jt[j*3+2] - Jt[p*3+2];
            float r0 = A[p*12 + m*4+0];
            float r1 = A[p*12 + m*4+1];
            float r2 = A[p*12 + m*4+2];
            float rt = A[p*12 + m*4+3];
            A[j*12 + m*4+0] = r0*Rl[0] + r1*Rl[3] + r2*Rl[6];
            A[j*12 + m*4+1] = r0*Rl[1] + r1*Rl[4] + r2*Rl[7];
            A[j*12 + m*4+2] = r0*Rl[2] + r1*Rl[5] + r2*Rl[8];
            A[j*12 + m*4+3] = r0*t0 + r1*t1 + r2*t2 + rt;
        }
    }
    __syncwarp();

    if (lane < NJ) {
        int j = lane;
        const float* Aj = &sA[warp][j*12];
        float jt0 = sJt[warp][j*3+0], jt1 = sJt[warp][j*3+1], jt2 = sJt[warp][j*3+2];
        __half* dst = &g_Arelh[(size_t)(b >> 2)*SLICE_ELEMS];
        int ncol0 = (b & 3)*12;
        #pragma unroll
        for (int m = 0; m < 3; m++) {
            float r0 = Aj[m*4+0], r1 = Aj[m*4+1], r2 = Aj[m*4+2];
            float t = Aj[m*4+3];
            out_joints[(b*NJ + j)*3 + m] = t;
            float trel = t - (r0*jt0 + r1*jt1 + r2*jt2);
            dst[tile_idx4(ncol0 + m*4 + 0, j)] = __float2half_rn(r0);
            dst[tile_idx4(ncol0 + m*4 + 1, j)] = __float2half_rn(r1);
            dst[tile_idx4(ncol0 + m*4 + 2, j)] = __float2half_rn(r2);
            dst[tile_idx4(ncol0 + m*4 + 3, j)] = __float2half_rn(trel);
        }
    }
}

// ---------------------------------------------------------------------------
// GEMM: v_posed = A(1024x224) @ B(224x20670), fp16 1-pass, k=32 chunks.
// Grid: blockIdx.x = mtile (FAST) so all 8 mtiles of an ntile run in the
// same wave -> B tiles are read from DRAM once and L2-shared.
// ---------------------------------------------------------------------------
#define STG_BYTES 16384

__global__ __launch_bounds__(256, 2)
void k_gemm() {
    __shared__ __align__(128) char sm[3][STG_BYTES];
    uint32_t sbase = smem_u32(sm);

    int tid = threadIdx.x;
    int lane = tid & 31;
    int wid = tid >> 5;
    int wm = wid & 3;
    int wn = wid >> 2;
    int g4 = lane >> 2;
    int t4 = lane & 3;
    int mtile = blockIdx.x;    // FAST dim
    int ntile = blockIdx.y;
    int n0 = ntile * 128;
    int m0 = mtile * 128;

    const char* srcAh = (const char*)&g_Asw_h[(size_t)mtile*NCHUNK*CHUNK_ELEMS];
    const char* srcBh = (const char*)&g_Bsw_h[(size_t)ntile*NCHUNK*CHUNK_ELEMS];

    int qa = lane >> 3, ra = lane & 7;
    uint32_t offA[2], offB[4];
    #pragma unroll
    for (int mf = 0; mf < 2; mf++) {
        int tr0 = 4*wm + 2*mf;
        int t = (tr0 + (qa & 1))*2 + (qa >> 1);
        offA[mf] = t*128 + ra*16;
    }
    #pragma unroll
    for (int p = 0; p < 4; p++) {
        int gA = 8*wn + 2*p;
        int t = (gA + (qa >> 1))*2 + (qa & 1);
        offB[p] = t*128 + ra*16;
    }

    auto load_chunk = [&](int s, int ck) {
        uint32_t d = sbase + s*STG_BYTES;
        size_t co = (size_t)ck * 8192;
        CP16(d + tid*16,          srcAh + co + tid*16);
        CP16(d + 4096 + tid*16,   srcAh + co + 4096 + tid*16);
        CP16(d + 8192 + tid*16,   srcBh + co + tid*16);
        CP16(d + 12288 + tid*16,  srcBh + co + 4096 + tid*16);
        asm volatile("cp.async.commit_group;" ::: "memory");
    };

    float d[2][8][4];
    #pragma unroll
    for (int mf = 0; mf < 2; mf++)
        #pragma unroll
        for (int f = 0; f < 8; f++)
            #pragma unroll
            for (int q = 0; q < 4; q++) d[mf][f][q] = 0.f;

    load_chunk(0, 0);
    load_chunk(1, 1);

    for (int ck = 0; ck < KCH; ck++) {
        int s = ck % 3;
        if (ck < KCH-1) asm volatile("cp.async.wait_group 1;" ::: "memory");
        else            asm volatile("cp.async.wait_group 0;" ::: "memory");
        __syncthreads();
        if (ck + 2 < KCH) load_chunk((ck + 2) % 3, ck + 2);

        #pragma unroll
        for (int ks2 = 0; ks2 < 2; ks2++) {
            uint32_t sba = sbase + s*STG_BYTES + ks2*4096;
            uint32_t sbb = sbase + s*STG_BYTES + 8192 + ks2*4096;
            unsigned ah[2][4];
            #pragma unroll
            for (int mf = 0; mf < 2; mf++) LDSM4(ah[mf], sba + offA[mf]);
            #pragma unroll
            for (int p = 0; p < 4; p++) {
                unsigned bh[4];
                LDSM4(bh, sbb + offB[p]);
                #pragma unroll
                for (int mf = 0; mf < 2; mf++) {
                    MMA_F16(d[mf][2*p],   ah[mf], bh[0], bh[1]);
                    MMA_F16(d[mf][2*p+1], ah[mf], bh[2], bh[3]);
                }
            }
        }
    }

    #pragma unroll
    for (int mf = 0; mf < 2; mf++) {
        #pragma unroll
        for (int f = 0; f < 8; f++) {
            int row = m0 + 32*wm + 16*mf + g4;
            int cg = n0 + 64*wn + 8*f + 2*t4;
            if (cg < N3) {
                *(float2*)&g_vposed[(size_t)row*N3 + cg] =
                    make_float2(d[mf][f][0], d[mf][f][1]);
                *(float2*)&g_vposed[(size_t)(row+8)*N3 + cg] =
                    make_float2(d[mf][f][2], d[mf][f][3]);
            }
        }
    }
}

// ---------------------------------------------------------------------------
// LBS: block = 128 vertices x 32 batches (8 slices of 4), fp16 2-pass:
// T = (W_hi + W_lo) @ Arel_hi. W/Arel pre-swizzled via cp.async.
// Warp tiling 4m x 2n; T tile XOR-swizzled.
// ---------------------------------------------------------------------------
union ULbs {
    __half Wst[2][WT_ELEMS];   // 16 KB (hi at 0, lo at +8192 B)
    float T[LVB*TST];          // 32 KB
};

__global__ __launch_bounds__(256, 3)
void k_lbs(float* __restrict__ out_v) {
    __shared__ ULbs u;
    __shared__ __align__(128) __half sRh[2][SLICE_ELEMS];

    int tid = threadIdx.x;
    int lane = tid & 31;
    int wid = tid >> 5;
    int wm = wid & 3;
    int wn = wid >> 2;
    int g4 = lane >> 2;
    int t4 = lane & 3;
    int qa = lane >> 3, ra = lane & 7;
    int v0 = blockIdx.x * LVB;
    int b0 = blockIdx.y * LBB;
    int slice0 = b0 >> 2;

    {
        uint32_t wb = smem_u32(u.Wst);
        const char* srcWh = (const char*)&g_Wswh[(size_t)blockIdx.x*WT_ELEMS];
        const char* srcWl = (const char*)&g_Wswl[(size_t)blockIdx.x*WT_ELEMS];
        CP16(wb + tid*16,          srcWh + tid*16);
        CP16(wb + 4096 + tid*16,   srcWh + 4096 + tid*16);
        CP16(wb + 8192 + tid*16,   srcWl + tid*16);
        CP16(wb + 12288 + tid*16,  srcWl + 4096 + tid*16);
        asm volatile("cp.async.commit_group;" ::: "memory");
    }
    auto load_slice = [&](int buf, int s) {
        if (tid < 192)
            CP16(smem_u32(sRh[buf]) + tid*16,
                 (const char*)&g_Arelh[(size_t)(slice0 + s)*SLICE_ELEMS] + tid*16);
        asm volatile("cp.async.commit_group;" ::: "memory");
    };
    load_slice(0, 0);
    load_slice(1, 1);

    asm volatile("cp.async.wait_group 2;" ::: "memory");
    __syncthreads();

    uint32_t wbase = smem_u32(u.Wst);
    unsigned wh[2][2][4], wl[2][2][4];
    #pragma unroll
    for (int mf = 0; mf < 2; mf++) {
        #pragma unroll
        for (int ks = 0; ks < 2; ks++) {
            int t = (4*wm + 2*mf + (qa & 1))*4 + 2*ks + (qa >> 1);
            LDSM4(wh[mf][ks], wbase + t*128 + ra*16);
            LDSM4(wl[mf][ks], wbase + 8192 + t*128 + ra*16);
        }
    }

    int vert = tid & 127;
    int half_ = tid >> 7;
    int vgc = v0 + vert;
    float4* T4 = (float4*)u.T;
    int vx = vert & 7;

    for (int s = 0; s < NSLICE; s++) {
        if (s < NSLICE-1) asm volatile("cp.async.wait_group 1;" ::: "memory");
        else              asm volatile("cp.async.wait_group 0;" ::: "memory");
        __syncthreads();

        uint32_t rb = smem_u32(sRh[s & 1]);
        unsigned bp[3][4];
        #pragma unroll
        for (int p = 0; p < 3; p++) {
            int np = 3*wn + p;
            LDSM4(bp[p], rb + (np*4 + qa)*128 + ra*16);
        }

        float d[2][3][4];
        #pragma unroll
        for (int mf = 0; mf < 2; mf++)
            #pragma unroll
            for (int p = 0; p < 3; p++)
                #pragma unroll
                for (int q = 0; q < 4; q++) d[mf][p][q] = 0.f;

        #pragma unroll
        for (int ks = 0; ks < 2; ks++) {
            #pragma unroll
            for (int p = 0; p < 3; p++) {
                #pragma unroll
                for (int mf = 0; mf < 2; mf++) {
                    MMA_F16(d[mf][p], wh[mf][ks], bp[p][2*ks], bp[p][2*ks+1]);
                    MMA_F16(d[mf][p], wl[mf][ks], bp[p][2*ks], bp[p][2*ks+1]);
                }
            }
        }

        #pragma unroll
        for (int mf = 0; mf < 2; mf++) {
            #pragma unroll
            for (int p = 0; p < 3; p++) {
                int row = 32*wm + 16*mf + g4;
                int col = 24*wn + 8*p + 2*t4;
                int g = col >> 2;
                int off = col & 3;
                int rx = row & 7;
                float* p0 = &u.T[row*TST     + ((g ^ rx) << 2) + off];
                float* p1 = &u.T[(row+8)*TST + ((g ^ rx) << 2) + off];
                *(float2*)p0 = make_float2(d[mf][p][0], d[mf][p][1]);
                *(float2*)p1 = make_float2(d[mf][p][2], d[mf][p][3]);
            }
        }
        __syncthreads();

        if (s + 2 < NSLICE) load_slice(s & 1, s + 2);

        if (vgc < NV) {
            #pragma unroll
            for (int x = 0; x < 2; x++) {
                int bb = half_*2 + x;
                int bglob = b0 + s*4 + bb;
                int gbase = 3*bb;
                float4 A0 = T4[vert*16 + ((gbase    ) ^ vx)];
                float4 A1 = T4[vert*16 + ((gbase + 1) ^ vx)];
                float4 A2 = T4[vert*16 + ((gbase + 2) ^ vx)];
                size_t vp = (size_t)bglob*N3 + (size_t)vgc*3;
                float px = g_vposed[vp], py = g_vposed[vp+1], pz = g_vposed[vp+2];
                float ox = A0.x*px + A0.y*py + A0.z*pz + A0.w;
                float oy = A1.x*px + A1.y*py + A1.z*pz + A1.w;
                float oz = A2.x*px + A2.y*py + A2.z*pz + A2.w;
                size_t ob = ((size_t)bglob*NV + vgc)*3;
                out_v[ob]   = ox;
                out_v[ob+1] = oy;
                out_v[ob+2] = oz;
            }
        }
    }
}

// ---------------------------------------------------------------------------
extern "C" void kernel_launch(void* const* d_in, const int* in_sizes, int n_in,
                              void* d_out, int out_size) {
    const float* betas = (const float*)d_in[0];
    const float* grot  = (const float*)d_in[1];
    const float* bpose = (const float*)d_in[2];
    const float* vt    = (const float*)d_in[3];
    const float* sd    = (const float*)d_in[4];
    const float* pd    = (const float*)d_in[5];
    const float* JR    = (const float*)d_in[6];
    const float* w     = (const float*)d_in[7];
    float* out = (float*)d_out;
    float* out_vertices = out;
    float* out_joints = out + (size_t)BATCH*NV*3;

    k_prep<<<PB_BLOCKS + PW_BLOCKS + NJ*3, 256>>>(pd, sd, vt, w, JR);
    k_joints<<<BATCH/8, 256>>>(betas, grot, bpose, out_joints);
    k_gemm<<<dim3(MTILES, NTILES), 256>>>();
    k_lbs<<<dim3((NV + LVB - 1)/LVB, BATCH/LBB), 256>>>(out_vertices);
}